// round 9
// baseline (speedup 1.0000x reference)
#include <cuda_runtime.h>
#include <math.h>
#include <stdint.h>

#define BSZ    2048
#define DM     1024
#define HEADS  4
#define KD     256
#define HALFD  128
#define NK     512
#define KNN    32
#define ROWS   (BSZ*HEADS)   /* 8192 */

// ---------------- scratch (static device globals; no allocation) ----------------
__device__ float g_q  [BSZ*DM];          // q: [2048][1024] == [8192][256]
__device__ float g_s  [ROWS*2*NK];       // scores: [8192][1024]
__device__ float g_tv [ROWS*2*KNN];      // stage-1 top values (descending)
__device__ int   g_ti [ROWS*2*KNN];      // stage-1 top indices
__device__ float g_w  [ROWS*KNN];        // final softmax weights
__device__ int   g_idx[ROWS*KNN];        // final value-row indices

// ---------- packed f32x2 helpers ----------
__device__ __forceinline__ unsigned long long pack_dup(float a) {
    unsigned long long r;
    asm("mov.b64 %0, {%1, %1};" : "=l"(r) : "r"(__float_as_uint(a)));
    return r;
}
__device__ __forceinline__ unsigned long long pack2(float lo, float hi) {
    unsigned long long r;
    asm("mov.b64 %0, {%1, %2};" : "=l"(r) : "r"(__float_as_uint(lo)), "r"(__float_as_uint(hi)));
    return r;
}
__device__ __forceinline__ void fma2(unsigned long long& d, unsigned long long a,
                                     unsigned long long b) {
    asm("fma.rn.f32x2 %0, %1, %2, %0;" : "+l"(d) : "l"(a), "l"(b));
}
__device__ __forceinline__ void unpack2(unsigned long long v, float& lo, float& hi) {
    uint32_t l, h;
    asm("mov.b64 {%0, %1}, %2;" : "=r"(l), "=r"(h) : "l"(v));
    lo = __uint_as_float(l); hi = __uint_as_float(h);
}

// ============================================================================
// K1: q = x @ W^T + b  (M=2048, N=1024, K=1024, fp32)  — R5 configuration
// 128x128 tile, BK=16, 256 thr, 8x8 micro, reg-staged double buffering,
// one __syncthreads per K-chunk, FFMA2 inner loop.
// ============================================================================
__global__ void __launch_bounds__(256) k_qproj(const float* __restrict__ x,
                                               const float* __restrict__ W,
                                               const float* __restrict__ bq) {
    __shared__ float As[2][16][132];
    __shared__ float Bs[2][16][132];
    const int m0 = blockIdx.y * 128;
    const int n0 = blockIdx.x * 128;
    const int tid = threadIdx.x;
    const int tr = (tid >> 4) * 8;
    const int tc = (tid & 15) * 8;
    const int lrow = tid >> 2;          // 0..63
    const int lk4  = tid & 3;           // float4 index within BK=16

    const float* pa0 = x + (size_t)(m0 + lrow)      * DM + lk4 * 4;
    const float* pa1 = x + (size_t)(m0 + lrow + 64) * DM + lk4 * 4;
    const float* pb0 = W + (size_t)(n0 + lrow)      * DM + lk4 * 4;
    const float* pb1 = W + (size_t)(n0 + lrow + 64) * DM + lk4 * 4;

    unsigned long long acc[8][4];
#pragma unroll
    for (int i = 0; i < 8; i++)
#pragma unroll
        for (int j = 0; j < 4; j++) acc[i][j] = 0ULL;

    float4 ra0 = *(const float4*)pa0;
    float4 ra1 = *(const float4*)pa1;
    float4 rb0 = *(const float4*)pb0;
    float4 rb1 = *(const float4*)pb1;
    {
        As[0][lk4*4+0][lrow]    = ra0.x; As[0][lk4*4+1][lrow]    = ra0.y;
        As[0][lk4*4+2][lrow]    = ra0.z; As[0][lk4*4+3][lrow]    = ra0.w;
        As[0][lk4*4+0][lrow+64] = ra1.x; As[0][lk4*4+1][lrow+64] = ra1.y;
        As[0][lk4*4+2][lrow+64] = ra1.z; As[0][lk4*4+3][lrow+64] = ra1.w;
        Bs[0][lk4*4+0][lrow]    = rb0.x; Bs[0][lk4*4+1][lrow]    = rb0.y;
        Bs[0][lk4*4+2][lrow]    = rb0.z; Bs[0][lk4*4+3][lrow]    = rb0.w;
        Bs[0][lk4*4+0][lrow+64] = rb1.x; Bs[0][lk4*4+1][lrow+64] = rb1.y;
        Bs[0][lk4*4+2][lrow+64] = rb1.z; Bs[0][lk4*4+3][lrow+64] = rb1.w;
    }
    __syncthreads();

    for (int c = 0; c < 64; c++) {
        const int cur = c & 1;
        if (c < 63) {
            const int k0 = (c + 1) * 16;
            ra0 = *(const float4*)(pa0 + k0);
            ra1 = *(const float4*)(pa1 + k0);
            rb0 = *(const float4*)(pb0 + k0);
            rb1 = *(const float4*)(pb1 + k0);
        }
#pragma unroll
        for (int kk = 0; kk < 16; kk++) {
            float4 a0 = *(const float4*)&As[cur][kk][tr];
            float4 a1 = *(const float4*)&As[cur][kk][tr + 4];
            float4 b0 = *(const float4*)&Bs[cur][kk][tc];
            float4 b1 = *(const float4*)&Bs[cur][kk][tc + 4];
            unsigned long long bp[4];
            bp[0] = pack2(b0.x, b0.y); bp[1] = pack2(b0.z, b0.w);
            bp[2] = pack2(b1.x, b1.y); bp[3] = pack2(b1.z, b1.w);
            float a[8] = {a0.x,a0.y,a0.z,a0.w,a1.x,a1.y,a1.z,a1.w};
#pragma unroll
            for (int i = 0; i < 8; i++) {
                unsigned long long ad = pack_dup(a[i]);
#pragma unroll
                for (int j = 0; j < 4; j++) fma2(acc[i][j], ad, bp[j]);
            }
        }
        if (c < 63) {
            const int nxt = 1 - cur;
            As[nxt][lk4*4+0][lrow]    = ra0.x; As[nxt][lk4*4+1][lrow]    = ra0.y;
            As[nxt][lk4*4+2][lrow]    = ra0.z; As[nxt][lk4*4+3][lrow]    = ra0.w;
            As[nxt][lk4*4+0][lrow+64] = ra1.x; As[nxt][lk4*4+1][lrow+64] = ra1.y;
            As[nxt][lk4*4+2][lrow+64] = ra1.z; As[nxt][lk4*4+3][lrow+64] = ra1.w;
            Bs[nxt][lk4*4+0][lrow]    = rb0.x; Bs[nxt][lk4*4+1][lrow]    = rb0.y;
            Bs[nxt][lk4*4+2][lrow]    = rb0.z; Bs[nxt][lk4*4+3][lrow]    = rb0.w;
            Bs[nxt][lk4*4+0][lrow+64] = rb1.x; Bs[nxt][lk4*4+1][lrow+64] = rb1.y;
            Bs[nxt][lk4*4+2][lrow+64] = rb1.z; Bs[nxt][lk4*4+3][lrow+64] = rb1.w;
        }
        __syncthreads();
    }

#pragma unroll
    for (int i = 0; i < 8; i++) {
        float* op = g_q + (size_t)(m0 + tr + i) * DM + n0 + tc;
        float r[8];
#pragma unroll
        for (int j = 0; j < 4; j++) unpack2(acc[i][j], r[2*j], r[2*j+1]);
#pragma unroll
        for (int j = 0; j < 8; j++) op[j] = r[j] + bq[n0 + tc + j];
    }
}

// ============================================================================
// K2: s1 = q1 @ keys^T, s2 = q2 @ keys^T  packed as S[8192][1024]
// NOW 128x128 tile (K1's balanced loop shape), BK=16 (8 chunks), 256 thr,
// 8x8 micro, reg-staged double buffering, FFMA2. Bit-identical accumulation.
// ============================================================================
__global__ void __launch_bounds__(256) k_scores(const float* __restrict__ keys) {
    __shared__ float As[2][16][132];
    __shared__ float Bs[2][16][132];
    const int r0 = blockIdx.y * 128;
    const int j0 = blockIdx.x * 128;            // 0,128,...,896 (within halves)
    const int half = (j0 >= NK) ? 1 : 0;
    const int jb = j0 - half * NK;              // 0..384, 128-aligned
    const int tid = threadIdx.x;
    const int tr = (tid >> 4) * 8;
    const int tc = (tid & 15) * 8;
    const int lrow = tid >> 2;          // 0..63
    const int lk4  = tid & 3;

    const float* pa0 = g_q + (size_t)(r0 + lrow)      * KD + half * HALFD + lk4 * 4;
    const float* pa1 = g_q + (size_t)(r0 + lrow + 64) * KD + half * HALFD + lk4 * 4;
    const float* pb0 = keys + (size_t)(jb + lrow)      * HALFD + lk4 * 4;
    const float* pb1 = keys + (size_t)(jb + lrow + 64) * HALFD + lk4 * 4;

    unsigned long long acc[8][4];
#pragma unroll
    for (int i = 0; i < 8; i++)
#pragma unroll
        for (int j = 0; j < 4; j++) acc[i][j] = 0ULL;

    float4 ra0 = *(const float4*)pa0;
    float4 ra1 = *(const float4*)pa1;
    float4 rb0 = *(const float4*)pb0;
    float4 rb1 = *(const float4*)pb1;
    {
        As[0][lk4*4+0][lrow]    = ra0.x; As[0][lk4*4+1][lrow]    = ra0.y;
        As[0][lk4*4+2][lrow]    = ra0.z; As[0][lk4*4+3][lrow]    = ra0.w;
        As[0][lk4*4+0][lrow+64] = ra1.x; As[0][lk4*4+1][lrow+64] = ra1.y;
        As[0][lk4*4+2][lrow+64] = ra1.z; As[0][lk4*4+3][lrow+64] = ra1.w;
        Bs[0][lk4*4+0][lrow]    = rb0.x; Bs[0][lk4*4+1][lrow]    = rb0.y;
        Bs[0][lk4*4+2][lrow]    = rb0.z; Bs[0][lk4*4+3][lrow]    = rb0.w;
        Bs[0][lk4*4+0][lrow+64] = rb1.x; Bs[0][lk4*4+1][lrow+64] = rb1.y;
        Bs[0][lk4*4+2][lrow+64] = rb1.z; Bs[0][lk4*4+3][lrow+64] = rb1.w;
    }
    __syncthreads();

    for (int c = 0; c < 8; c++) {
        const int cur = c & 1;
        if (c < 7) {
            const int k0 = (c + 1) * 16;
            ra0 = *(const float4*)(pa0 + k0);
            ra1 = *(const float4*)(pa1 + k0);
            rb0 = *(const float4*)(pb0 + k0);
            rb1 = *(const float4*)(pb1 + k0);
        }
#pragma unroll
        for (int kk = 0; kk < 16; kk++) {
            float4 a0 = *(const float4*)&As[cur][kk][tr];
            float4 a1 = *(const float4*)&As[cur][kk][tr + 4];
            float4 b0 = *(const float4*)&Bs[cur][kk][tc];
            float4 b1 = *(const float4*)&Bs[cur][kk][tc + 4];
            unsigned long long bp[4];
            bp[0] = pack2(b0.x, b0.y); bp[1] = pack2(b0.z, b0.w);
            bp[2] = pack2(b1.x, b1.y); bp[3] = pack2(b1.z, b1.w);
            float a[8] = {a0.x,a0.y,a0.z,a0.w,a1.x,a1.y,a1.z,a1.w};
#pragma unroll
            for (int i = 0; i < 8; i++) {
                unsigned long long ad = pack_dup(a[i]);
#pragma unroll
                for (int j = 0; j < 4; j++) fma2(acc[i][j], ad, bp[j]);
            }
        }
        if (c < 7) {
            const int nxt = 1 - cur;
            As[nxt][lk4*4+0][lrow]    = ra0.x; As[nxt][lk4*4+1][lrow]    = ra0.y;
            As[nxt][lk4*4+2][lrow]    = ra0.z; As[nxt][lk4*4+3][lrow]    = ra0.w;
            As[nxt][lk4*4+0][lrow+64] = ra1.x; As[nxt][lk4*4+1][lrow+64] = ra1.y;
            As[nxt][lk4*4+2][lrow+64] = ra1.z; As[nxt][lk4*4+3][lrow+64] = ra1.w;
            Bs[nxt][lk4*4+0][lrow]    = rb0.x; Bs[nxt][lk4*4+1][lrow]    = rb0.y;
            Bs[nxt][lk4*4+2][lrow]    = rb0.z; Bs[nxt][lk4*4+3][lrow]    = rb0.w;
            Bs[nxt][lk4*4+0][lrow+64] = rb1.x; Bs[nxt][lk4*4+1][lrow+64] = rb1.y;
            Bs[nxt][lk4*4+2][lrow+64] = rb1.z; Bs[nxt][lk4*4+3][lrow+64] = rb1.w;
        }
        __syncthreads();
    }

#pragma unroll
    for (int i = 0; i < 8; i++) {
        float r[8];
#pragma unroll
        for (int j = 0; j < 4; j++) unpack2(acc[i][j], r[2*j], r[2*j+1]);
        float* op = g_s + (size_t)(r0 + tr + i) * 1024 + j0 + tc;
        *(float4*)(op + 0) = make_float4(r[0], r[1], r[2], r[3]);
        *(float4*)(op + 4) = make_float4(r[4], r[5], r[6], r[7]);
    }
}

// ============================================================================
// K3: stage-1 top-32 of 512 per (row, half). Batcher sort + tournament merge.
// (R5 configuration — 16384 warp-tasks.)
// ============================================================================
__global__ void __launch_bounds__(256) k_topk1() {
    __shared__ float sv[8][16][32];
    __shared__ short sg[8][16][32];
    const int wid  = threadIdx.x >> 5;
    const int lane = threadIdx.x & 31;
    const int task = blockIdx.x * 8 + wid;
    const int r = task >> 1;
    const int half = task & 1;
    const float* s = g_s + (size_t)r * 1024 + half * NK;

    float vv[16]; int tt[16];
#pragma unroll
    for (int t = 0; t < 16; t++) { vv[t] = s[t * 32 + lane]; tt[t] = t; }

#pragma unroll
    for (int p = 1; p < 16; p <<= 1) {
#pragma unroll
        for (int k = p; k >= 1; k >>= 1) {
#pragma unroll
            for (int j = k & (p - 1); j + k < 16; j += 2 * k) {
#pragma unroll
                for (int i = 0; i < k; i++) {
                    if (((i + j) / (2 * p)) == ((i + j + k) / (2 * p))) {
                        const int xa = i + j, xb = i + j + k;
                        bool sw = (vv[xb] > vv[xa]) ||
                                  (vv[xb] == vv[xa] && tt[xb] < tt[xa]);
                        float fv = sw ? vv[xb] : vv[xa];
                        float gv = sw ? vv[xa] : vv[xb];
                        int   ft = sw ? tt[xb] : tt[xa];
                        int   gt = sw ? tt[xa] : tt[xb];
                        vv[xa] = fv; vv[xb] = gv; tt[xa] = ft; tt[xb] = gt;
                    }
                }
            }
        }
    }

#pragma unroll
    for (int t = 0; t < 16; t++) {
        sv[wid][t][lane] = vv[t];
        sg[wid][t][lane] = (short)(tt[t] * 32 + lane);
    }
    __syncwarp();

    int p = 0;
    float cur = sv[wid][0][lane];
    int   cgi = sg[wid][0][lane];
    float outv = 0.f; int outi = 0;

    for (int sel = 0; sel < 32; sel++) {
        float bv = cur; int bgi = cgi;
#pragma unroll
        for (int off = 16; off > 0; off >>= 1) {
            float ov = __shfl_xor_sync(0xffffffffu, bv, off);
            int   oi = __shfl_xor_sync(0xffffffffu, bgi, off);
            if (ov > bv || (ov == bv && oi < bgi)) { bv = ov; bgi = oi; }
        }
        if (lane == sel) { outv = bv; outi = bgi; }
        p += (cgi == bgi);
        if (p < 16) {
            cur = sv[wid][p][lane];
            cgi = sg[wid][p][lane];
        } else {
            cur = -INFINITY;
            cgi = 1024 + lane;
        }
    }
    g_tv[(size_t)task * 32 + lane] = outv;
    g_ti[(size_t)task * 32 + lane] = outi;
}

// ============================================================================
// K4: combine 32x32 sums -> top-32 -> softmax (tournament merge). (R5 config.)
// ============================================================================
__global__ void __launch_bounds__(256) k_combine() {
    const int wid  = threadIdx.x >> 5;
    const int lane = threadIdx.x & 31;
    const int r = blockIdx.x * 8 + wid;

    const float v1 = g_tv[(size_t)(r * 2 + 0) * 32 + lane];
    const int   i1 = g_ti[(size_t)(r * 2 + 0) * 32 + lane];
    const float v2 = g_tv[(size_t)(r * 2 + 1) * 32 + lane];
    const int   i2 = g_ti[(size_t)(r * 2 + 1) * 32 + lane];

    int p = 0;
    float cur = v1 + __shfl_sync(0xffffffffu, v2, 0);
    int   fi  = lane * 32;
    float myval = 0.f; int myidx = 0;

    for (int sel = 0; sel < 32; sel++) {
        float bv = cur; int bfi = fi;
#pragma unroll
        for (int off = 16; off > 0; off >>= 1) {
            float ov = __shfl_xor_sync(0xffffffffu, bv, off);
            int   oi = __shfl_xor_sync(0xffffffffu, bfi, off);
            if (ov > bv || (ov == bv && oi < bfi)) { bv = ov; bfi = oi; }
        }
        const int a = bfi >> 5, b = bfi & 31;
        const int vid = __shfl_sync(0xffffffffu, i1, a) * NK +
                        __shfl_sync(0xffffffffu, i2, b);
        if (lane == sel) { myval = bv; myidx = vid; }
        p += (fi == bfi);
        float s2p = __shfl_sync(0xffffffffu, v2, p & 31);
        if (p < 32) {
            cur = v1 + s2p;
            fi  = lane * 32 + p;
        } else {
            cur = -INFINITY;
            fi  = 2048 + lane;
        }
    }

    const float m = __shfl_sync(0xffffffffu, myval, 0);
    float e = expf(myval - m);
    float sum = e;
#pragma unroll
    for (int off = 16; off > 0; off >>= 1)
        sum += __shfl_xor_sync(0xffffffffu, sum, off);
    g_w  [(size_t)r * 32 + lane] = e / sum;
    g_idx[(size_t)r * 32 + lane] = myidx;
}

// ============================================================================
// K5: out[b,:] = sum_{k=0..127} w[b,k] * values[idx[b,k], :]  (R5 config)
// ============================================================================
__global__ void __launch_bounds__(256) k_gather(const float* __restrict__ values,
                                                float* __restrict__ out) {
    const int b = blockIdx.x;
    const int tid = threadIdx.x;
    __shared__ float sw[128];
    __shared__ int   si[128];
    if (tid < 128) {
        sw[tid] = g_w  [(size_t)b * 128 + tid];
        si[tid] = g_idx[(size_t)b * 128 + tid];
    }
    __syncthreads();

    float4 acc = make_float4(0.f, 0.f, 0.f, 0.f);
#pragma unroll 8
    for (int k = 0; k < 128; k++) {
        const float4 v = ((const float4*)(values + (size_t)si[k] * DM))[tid];
        const float w = sw[k];
        acc.x += w * v.x; acc.y += w * v.y;
        acc.z += w * v.z; acc.w += w * v.w;
    }
    ((float4*)out)[(size_t)b * 256 + tid] = acc;
}

// ============================================================================
extern "C" void kernel_launch(void* const* d_in, const int* in_sizes, int n_in,
                              void* d_out, int out_size) {
    const float* x      = (const float*)d_in[0];
    const float* W      = (const float*)d_in[1];
    const float* bq     = (const float*)d_in[2];
    const float* keys   = (const float*)d_in[3];
    const float* values = (const float*)d_in[4];
    float* out = (float*)d_out;

    k_qproj  <<<dim3(DM / 128, BSZ / 128), 256>>>(x, W, bq);
    k_scores <<<dim3(1024 / 128, ROWS / 128), 256>>>(keys);
    k_topk1  <<<(ROWS * 2) / 8, 256>>>();
    k_combine<<<ROWS / 8, 256>>>();
    k_gather <<<BSZ, 256>>>(values, out);
}

// round 11
// speedup vs baseline: 1.0717x; 1.0717x over previous
#include <cuda_runtime.h>
#include <math.h>
#include <stdint.h>

#define BSZ    2048
#define DM     1024
#define HEADS  4
#define KD     256
#define HALFD  128
#define NK     512
#define KNN    32
#define ROWS   (BSZ*HEADS)   /* 8192 */

// ---------------- scratch (static device globals; no allocation) ----------------
__device__ float g_q  [BSZ*DM];          // q: [2048][1024] == [8192][256]
__device__ float g_s  [ROWS*2*NK];       // scores: [8192][1024]
__device__ float g_tv [ROWS*2*KNN];      // stage-1 top values (descending)
__device__ int   g_ti [ROWS*2*KNN];      // stage-1 top indices
__device__ float g_w  [ROWS*KNN];        // final softmax weights
__device__ int   g_idx[ROWS*KNN];        // final value-row indices

// ---------- packed f32x2 helpers ----------
__device__ __forceinline__ unsigned long long pack_dup(float a) {
    unsigned long long r;
    asm("mov.b64 %0, {%1, %1};" : "=l"(r) : "r"(__float_as_uint(a)));
    return r;
}
__device__ __forceinline__ unsigned long long pack2(float lo, float hi) {
    unsigned long long r;
    asm("mov.b64 %0, {%1, %2};" : "=l"(r) : "r"(__float_as_uint(lo)), "r"(__float_as_uint(hi)));
    return r;
}
__device__ __forceinline__ void fma2(unsigned long long& d, unsigned long long a,
                                     unsigned long long b) {
    asm("fma.rn.f32x2 %0, %1, %2, %0;" : "+l"(d) : "l"(a), "l"(b));
}
__device__ __forceinline__ void unpack2(unsigned long long v, float& lo, float& hi) {
    uint32_t l, h;
    asm("mov.b64 {%0, %1}, %2;" : "=r"(l), "=r"(h) : "l"(v));
    lo = __uint_as_float(l); hi = __uint_as_float(h);
}

// ---------- order-preserving float<->u32 map (no NaNs in this data) ----------
__device__ __forceinline__ uint32_t fkey(float f) {
    uint32_t u = __float_as_uint(f);
    return u ^ (uint32_t)(((int32_t)u >> 31) | 0x80000000);
}
__device__ __forceinline__ float funkey(uint32_t u) {
    u ^= (u & 0x80000000u) ? 0x80000000u : 0xFFFFFFFFu;
    return __uint_as_float(u);
}

// ============================================================================
// K1: q = x @ W^T + b  (M=2048, N=1024, K=1024, fp32)  — R5 configuration
// ============================================================================
__global__ void __launch_bounds__(256) k_qproj(const float* __restrict__ x,
                                               const float* __restrict__ W,
                                               const float* __restrict__ bq) {
    __shared__ float As[2][16][132];
    __shared__ float Bs[2][16][132];
    const int m0 = blockIdx.y * 128;
    const int n0 = blockIdx.x * 128;
    const int tid = threadIdx.x;
    const int tr = (tid >> 4) * 8;
    const int tc = (tid & 15) * 8;
    const int lrow = tid >> 2;          // 0..63
    const int lk4  = tid & 3;           // float4 index within BK=16

    const float* pa0 = x + (size_t)(m0 + lrow)      * DM + lk4 * 4;
    const float* pa1 = x + (size_t)(m0 + lrow + 64) * DM + lk4 * 4;
    const float* pb0 = W + (size_t)(n0 + lrow)      * DM + lk4 * 4;
    const float* pb1 = W + (size_t)(n0 + lrow + 64) * DM + lk4 * 4;

    unsigned long long acc[8][4];
#pragma unroll
    for (int i = 0; i < 8; i++)
#pragma unroll
        for (int j = 0; j < 4; j++) acc[i][j] = 0ULL;

    float4 ra0 = *(const float4*)pa0;
    float4 ra1 = *(const float4*)pa1;
    float4 rb0 = *(const float4*)pb0;
    float4 rb1 = *(const float4*)pb1;
    {
        As[0][lk4*4+0][lrow]    = ra0.x; As[0][lk4*4+1][lrow]    = ra0.y;
        As[0][lk4*4+2][lrow]    = ra0.z; As[0][lk4*4+3][lrow]    = ra0.w;
        As[0][lk4*4+0][lrow+64] = ra1.x; As[0][lk4*4+1][lrow+64] = ra1.y;
        As[0][lk4*4+2][lrow+64] = ra1.z; As[0][lk4*4+3][lrow+64] = ra1.w;
        Bs[0][lk4*4+0][lrow]    = rb0.x; Bs[0][lk4*4+1][lrow]    = rb0.y;
        Bs[0][lk4*4+2][lrow]    = rb0.z; Bs[0][lk4*4+3][lrow]    = rb0.w;
        Bs[0][lk4*4+0][lrow+64] = rb1.x; Bs[0][lk4*4+1][lrow+64] = rb1.y;
        Bs[0][lk4*4+2][lrow+64] = rb1.z; Bs[0][lk4*4+3][lrow+64] = rb1.w;
    }
    __syncthreads();

    for (int c = 0; c < 64; c++) {
        const int cur = c & 1;
        if (c < 63) {
            const int k0 = (c + 1) * 16;
            ra0 = *(const float4*)(pa0 + k0);
            ra1 = *(const float4*)(pa1 + k0);
            rb0 = *(const float4*)(pb0 + k0);
            rb1 = *(const float4*)(pb1 + k0);
        }
#pragma unroll
        for (int kk = 0; kk < 16; kk++) {
            float4 a0 = *(const float4*)&As[cur][kk][tr];
            float4 a1 = *(const float4*)&As[cur][kk][tr + 4];
            float4 b0 = *(const float4*)&Bs[cur][kk][tc];
            float4 b1 = *(const float4*)&Bs[cur][kk][tc + 4];
            unsigned long long bp[4];
            bp[0] = pack2(b0.x, b0.y); bp[1] = pack2(b0.z, b0.w);
            bp[2] = pack2(b1.x, b1.y); bp[3] = pack2(b1.z, b1.w);
            float a[8] = {a0.x,a0.y,a0.z,a0.w,a1.x,a1.y,a1.z,a1.w};
#pragma unroll
            for (int i = 0; i < 8; i++) {
                unsigned long long ad = pack_dup(a[i]);
#pragma unroll
                for (int j = 0; j < 4; j++) fma2(acc[i][j], ad, bp[j]);
            }
        }
        if (c < 63) {
            const int nxt = 1 - cur;
            As[nxt][lk4*4+0][lrow]    = ra0.x; As[nxt][lk4*4+1][lrow]    = ra0.y;
            As[nxt][lk4*4+2][lrow]    = ra0.z; As[nxt][lk4*4+3][lrow]    = ra0.w;
            As[nxt][lk4*4+0][lrow+64] = ra1.x; As[nxt][lk4*4+1][lrow+64] = ra1.y;
            As[nxt][lk4*4+2][lrow+64] = ra1.z; As[nxt][lk4*4+3][lrow+64] = ra1.w;
            Bs[nxt][lk4*4+0][lrow]    = rb0.x; Bs[nxt][lk4*4+1][lrow]    = rb0.y;
            Bs[nxt][lk4*4+2][lrow]    = rb0.z; Bs[nxt][lk4*4+3][lrow]    = rb0.w;
            Bs[nxt][lk4*4+0][lrow+64] = rb1.x; Bs[nxt][lk4*4+1][lrow+64] = rb1.y;
            Bs[nxt][lk4*4+2][lrow+64] = rb1.z; Bs[nxt][lk4*4+3][lrow+64] = rb1.w;
        }
        __syncthreads();
    }

#pragma unroll
    for (int i = 0; i < 8; i++) {
        float* op = g_q + (size_t)(m0 + tr + i) * DM + n0 + tc;
        float r[8];
#pragma unroll
        for (int j = 0; j < 4; j++) unpack2(acc[i][j], r[2*j], r[2*j+1]);
#pragma unroll
        for (int j = 0; j < 8; j++) op[j] = r[j] + bq[n0 + tc + j];
    }
}

// ============================================================================
// K2: s1 = q1 @ keys^T, s2 = q2 @ keys^T  packed as S[8192][1024]
// 128x64 tile, BK=16 (8 chunks), 256 thr, 8x4 micro — R5 configuration.
// ============================================================================
__global__ void __launch_bounds__(256) k_scores(const float* __restrict__ keys) {
    __shared__ float As[2][16][132];
    __shared__ float Bs[2][16][68];
    const int r0 = blockIdx.y * 128;
    const int j0 = blockIdx.x * 64;
    const int half = (j0 >= NK) ? 1 : 0;
    const int jb = j0 - half * NK;
    const int tid = threadIdx.x;
    const int tr = (tid >> 4) * 8;
    const int tc = (tid & 15) * 4;
    const int lrow = tid >> 2;          // 0..63
    const int lk4  = tid & 3;

    const float* pa0 = g_q + (size_t)(r0 + lrow)      * KD + half * HALFD + lk4 * 4;
    const float* pa1 = g_q + (size_t)(r0 + lrow + 64) * KD + half * HALFD + lk4 * 4;
    const float* pb0 = keys + (size_t)(jb + lrow) * HALFD + lk4 * 4;

    unsigned long long acc[8][2];
#pragma unroll
    for (int i = 0; i < 8; i++) { acc[i][0] = 0ULL; acc[i][1] = 0ULL; }

    float4 ra0 = *(const float4*)pa0;
    float4 ra1 = *(const float4*)pa1;
    float4 rb0 = *(const float4*)pb0;
    {
        As[0][lk4*4+0][lrow]    = ra0.x; As[0][lk4*4+1][lrow]    = ra0.y;
        As[0][lk4*4+2][lrow]    = ra0.z; As[0][lk4*4+3][lrow]    = ra0.w;
        As[0][lk4*4+0][lrow+64] = ra1.x; As[0][lk4*4+1][lrow+64] = ra1.y;
        As[0][lk4*4+2][lrow+64] = ra1.z; As[0][lk4*4+3][lrow+64] = ra1.w;
        Bs[0][lk4*4+0][lrow]    = rb0.x; Bs[0][lk4*4+1][lrow]    = rb0.y;
        Bs[0][lk4*4+2][lrow]    = rb0.z; Bs[0][lk4*4+3][lrow]    = rb0.w;
    }
    __syncthreads();

    for (int c = 0; c < 8; c++) {
        const int cur = c & 1;
        if (c < 7) {
            const int k0 = (c + 1) * 16;
            ra0 = *(const float4*)(pa0 + k0);
            ra1 = *(const float4*)(pa1 + k0);
            rb0 = *(const float4*)(pb0 + k0);
        }
#pragma unroll
        for (int kk = 0; kk < 16; kk++) {
            float4 a0 = *(const float4*)&As[cur][kk][tr];
            float4 a1 = *(const float4*)&As[cur][kk][tr + 4];
            float4 bb = *(const float4*)&Bs[cur][kk][tc];
            unsigned long long bp0 = pack2(bb.x, bb.y);
            unsigned long long bp1 = pack2(bb.z, bb.w);
            float a[8] = {a0.x,a0.y,a0.z,a0.w,a1.x,a1.y,a1.z,a1.w};
#pragma unroll
            for (int i = 0; i < 8; i++) {
                unsigned long long ad = pack_dup(a[i]);
                fma2(acc[i][0], ad, bp0);
                fma2(acc[i][1], ad, bp1);
            }
        }
        if (c < 7) {
            const int nxt = 1 - cur;
            As[nxt][lk4*4+0][lrow]    = ra0.x; As[nxt][lk4*4+1][lrow]    = ra0.y;
            As[nxt][lk4*4+2][lrow]    = ra0.z; As[nxt][lk4*4+3][lrow]    = ra0.w;
            As[nxt][lk4*4+0][lrow+64] = ra1.x; As[nxt][lk4*4+1][lrow+64] = ra1.y;
            As[nxt][lk4*4+2][lrow+64] = ra1.z; As[nxt][lk4*4+3][lrow+64] = ra1.w;
            Bs[nxt][lk4*4+0][lrow]    = rb0.x; Bs[nxt][lk4*4+1][lrow]    = rb0.y;
            Bs[nxt][lk4*4+2][lrow]    = rb0.z; Bs[nxt][lk4*4+3][lrow]    = rb0.w;
        }
        __syncthreads();
    }
#pragma unroll
    for (int i = 0; i < 8; i++) {
        float4 v;
        unpack2(acc[i][0], v.x, v.y);
        unpack2(acc[i][1], v.z, v.w);
        *(float4*)(g_s + (size_t)(r0 + tr + i) * 1024 + j0 + tc) = v;
    }
}

// ============================================================================
// K3: stage-1 top-32 of 512 per (row, half). Batcher sort (packed u32 keys)
// + tournament merge with REDUX.SYNC extraction. Refill reads smem only
// (divergence-safe; no collectives in the divergent path).
// ============================================================================
__global__ void __launch_bounds__(256) k_topk1() {
    __shared__ uint32_t su[8][16][32];
    __shared__ short    sg[8][16][32];
    const int wid  = threadIdx.x >> 5;
    const int lane = threadIdx.x & 31;
    const int task = blockIdx.x * 8 + wid;
    const int r = task >> 1;
    const int half = task & 1;
    const float* s = g_s + (size_t)r * 1024 + half * NK;

    uint32_t uu[16]; int tt[16];
#pragma unroll
    for (int t = 0; t < 16; t++) { uu[t] = fkey(s[t * 32 + lane]); tt[t] = t; }

    // Batcher odd-even mergesort: desc by packed key, tie -> lower t.
#pragma unroll
    for (int p = 1; p < 16; p <<= 1) {
#pragma unroll
        for (int k = p; k >= 1; k >>= 1) {
#pragma unroll
            for (int j = k & (p - 1); j + k < 16; j += 2 * k) {
#pragma unroll
                for (int i = 0; i < k; i++) {
                    if (((i + j) / (2 * p)) == ((i + j + k) / (2 * p))) {
                        const int xa = i + j, xb = i + j + k;
                        bool sw = (uu[xb] > uu[xa]) ||
                                  (uu[xb] == uu[xa] && tt[xb] < tt[xa]);
                        uint32_t fu = sw ? uu[xb] : uu[xa];
                        uint32_t gu = sw ? uu[xa] : uu[xb];
                        int      ft = sw ? tt[xb] : tt[xa];
                        int      gt = sw ? tt[xa] : tt[xb];
                        uu[xa] = fu; uu[xb] = gu; tt[xa] = ft; tt[xb] = gt;
                    }
                }
            }
        }
    }

#pragma unroll
    for (int t = 0; t < 16; t++) {
        su[wid][t][lane] = uu[t];
        sg[wid][t][lane] = (short)(tt[t] * 32 + lane);
    }
    __syncwarp();

    int p = 0;
    uint32_t cu  = su[wid][0][lane];
    uint32_t cgi = (uint32_t)sg[wid][0][lane];
    uint32_t outu = 0; int outi = 0;

    for (int sel = 0; sel < 32; sel++) {
        const uint32_t m = __reduce_max_sync(0xffffffffu, cu);
        const uint32_t cand = (cu == m) ? cgi : 0xFFFFFFFFu;
        const uint32_t g = __reduce_min_sync(0xffffffffu, cand);
        if (lane == sel) { outu = m; outi = (int)g; }
        if (cgi == g) {                         // smem-only refill: divergence-safe
            p++;
            if (p < 16) {
                cu  = su[wid][p][lane];
                cgi = (uint32_t)sg[wid][p][lane];
            } else {
                cu  = 0u;                       // below any real packed value
                cgi = 1024u + lane;             // unique, never selected
            }
        }
    }
    g_tv[(size_t)task * 32 + lane] = funkey(outu);
    g_ti[(size_t)task * 32 + lane] = outi;
}

// ============================================================================
// K4: combine 32x32 sums -> top-32 -> softmax. REDUX.SYNC extraction.
// The refill shuffle is executed UNIFORMLY by all lanes (pn computed per-lane,
// commit is conditional) — this fixes the R10 divergent-shfl UB.
// ============================================================================
__global__ void __launch_bounds__(256) k_combine() {
    const int wid  = threadIdx.x >> 5;
    const int lane = threadIdx.x & 31;
    const int r = blockIdx.x * 8 + wid;

    const float v1 = g_tv[(size_t)(r * 2 + 0) * 32 + lane];
    const int   i1 = g_ti[(size_t)(r * 2 + 0) * 32 + lane];
    const float v2 = g_tv[(size_t)(r * 2 + 1) * 32 + lane];
    const int   i2 = g_ti[(size_t)(r * 2 + 1) * 32 + lane];

    int p = 0;
    uint32_t cu = fkey(v1 + __shfl_sync(0xffffffffu, v2, 0));
    uint32_t fi = (uint32_t)(lane * 32);
    uint32_t myu = 0; int myidx = 0;

    for (int sel = 0; sel < 32; sel++) {
        const uint32_t m = __reduce_max_sync(0xffffffffu, cu);
        const uint32_t cand = (cu == m) ? fi : 0xFFFFFFFFu;
        const uint32_t g = __reduce_min_sync(0xffffffffu, cand);
        const int a = (int)(g >> 5), b = (int)(g & 31);
        const int vid = __shfl_sync(0xffffffffu, i1, a) * NK +
                        __shfl_sync(0xffffffffu, i2, b);
        if (lane == sel) { myu = m; myidx = vid; }

        const bool adv = (fi == g);
        const int pn = p + (adv ? 1 : 0);
        const float s2p = __shfl_sync(0xffffffffu, v2, pn & 31);  // uniform shfl
        if (adv) {
            p = pn;
            if (p < 32) {
                cu = fkey(v1 + s2p);
                fi = (uint32_t)(lane * 32 + p);
            } else {
                cu = 0u;
                fi = 2048u + lane;
            }
        }
    }

    const float myval = funkey(myu);
    const float mx = __shfl_sync(0xffffffffu, myval, 0);
    float e = expf(myval - mx);
    float sum = e;
#pragma unroll
    for (int off = 16; off > 0; off >>= 1)
        sum += __shfl_xor_sync(0xffffffffu, sum, off);
    g_w  [(size_t)r * 32 + lane] = e / sum;
    g_idx[(size_t)r * 32 + lane] = myidx;
}

// ============================================================================
// K5: out[b,:] = sum_{k=0..127} w[b,k] * values[idx[b,k], :]  (R5 config)
// ============================================================================
__global__ void __launch_bounds__(256) k_gather(const float* __restrict__ values,
                                                float* __restrict__ out) {
    const int b = blockIdx.x;
    const int tid = threadIdx.x;
    __shared__ float sw[128];
    __shared__ int   si[128];
    if (tid < 128) {
        sw[tid] = g_w  [(size_t)b * 128 + tid];
        si[tid] = g_idx[(size_t)b * 128 + tid];
    }
    __syncthreads();

    float4 acc = make_float4(0.f, 0.f, 0.f, 0.f);
#pragma unroll 8
    for (int k = 0; k < 128; k++) {
        const float4 v = ((const float4*)(values + (size_t)si[k] * DM))[tid];
        const float w = sw[k];
        acc.x += w * v.x; acc.y += w * v.y;
        acc.z += w * v.z; acc.w += w * v.w;
    }
    ((float4*)out)[(size_t)b * 256 + tid] = acc;
}

// ============================================================================
extern "C" void kernel_launch(void* const* d_in, const int* in_sizes, int n_in,
                              void* d_out, int out_size) {
    const float* x      = (const float*)d_in[0];
    const float* W      = (const float*)d_in[1];
    const float* bq     = (const float*)d_in[2];
    const float* keys   = (const float*)d_in[3];
    const float* values = (const float*)d_in[4];
    float* out = (float*)d_out;

    k_qproj  <<<dim3(DM / 128, BSZ / 128), 256>>>(x, W, bq);
    k_scores <<<dim3(1024 / 64, ROWS / 128), 256>>>(keys);
    k_topk1  <<<(ROWS * 2) / 8, 256>>>();
    k_combine<<<ROWS / 8, 256>>>();
    k_gather <<<BSZ, 256>>>(values, out);
}